// round 4
// baseline (speedup 1.0000x reference)
#include <cuda_runtime.h>

// Batched active-set (water-filling) projection — block-per-row, 4 warps/row,
// 8 elements/lane. Threshold-set formulation (phase-0 fill monotone
// decreasing -> lower set = {y < -fill}; phase-1 fill monotone increasing ->
// upper set = {y-u > -fill}). Per iteration: 8-elem scan, one packed (count,
// sum) warp butterfly, one smem float2 per warp, ONE __syncthreads
// (double-buffered slots), redundant 4-way total in every thread.

#define NCOLS 1024
#define WARPS 4
#define THREADS 128          // 8 elements per lane
#define EPL 8

__global__ __launch_bounds__(THREADS)
void proj_kernel(const float* __restrict__ y,
                 const float* __restrict__ upper,
                 float* __restrict__ out) {
    const int t    = threadIdx.x;
    const int lane = t & 31;
    const int wid  = t >> 5;
    const int row  = blockIdx.x;

    const float4* yrow = reinterpret_cast<const float4*>(y + (size_t)row * NCOLS);
    const float4* urow = reinterpret_cast<const float4*>(upper);

    // elements: float4 slots t and t+128
    float yv[EPL], uv[EPL];
    {
        const float4 a0 = yrow[t], a1 = yrow[t + 128];
        const float4 b0 = urow[t], b1 = urow[t + 128];
        yv[0]=a0.x; yv[1]=a0.y; yv[2]=a0.z; yv[3]=a0.w;
        yv[4]=a1.x; yv[5]=a1.y; yv[6]=a1.z; yv[7]=a1.w;
        uv[0]=b0.x; uv[1]=b0.y; uv[2]=b0.z; uv[3]=b0.w;
        uv[4]=b1.x; uv[5]=b1.y; uv[6]=b1.z; uv[7]=b1.w;
    }

    __shared__ float2 red[2][WARPS];   // double-buffered per-warp partials

    // ---- initial s0 = sum(y) ----
    float s0;
    {
        float p = 0.0f;
        #pragma unroll
        for (int e = 0; e < EPL; e++) p += yv[e];
        #pragma unroll
        for (int o = 16; o; o >>= 1) p += __shfl_xor_sync(0xffffffffu, p, o);
        if (lane == 0) red[0][wid] = make_float2(p, 0.0f);
        __syncthreads();
        s0 = red[0][0].x + red[0][1].x + red[0][2].x + red[0][3].x;
    }

    const float base0 = 512.0f - s0;
    float fill = base0 * (1.0f / 1024.0f);

    int   it = 0;
    float maskT0 = 0.0f;
    bool  p0conv = false;
    float cntF = 0.0f, dsF = 0.0f;

    // ---- phase 0: lower clamps (threshold scan on y) ----
    {
        float prev = -1.0f;
        for (;;) {
            ++it;
            const int pb = it & 1;
            const float T = -fill;
            float c = 0.0f, d = 0.0f;
            #pragma unroll
            for (int e = 0; e < EPL; e++) {
                const bool p = yv[e] < T;
                c += p ? 1.0f : 0.0f;
                d += p ? yv[e] : 0.0f;
            }
            #pragma unroll
            for (int o = 16; o; o >>= 1) {
                c += __shfl_xor_sync(0xffffffffu, c, o);
                d += __shfl_xor_sync(0xffffffffu, d, o);
            }
            if (lane == 0) red[pb][wid] = make_float2(c, d);
            __syncthreads();
            const float C = red[pb][0].x + red[pb][1].x + red[pb][2].x + red[pb][3].x;
            const float D = red[pb][0].y + red[pb][1].y + red[pb][2].y + red[pb][3].y;
            maskT0 = T; cntF = C; dsF = D;
            if (C == prev) { p0conv = true; break; }   // phase-advance round
            prev = C;
            fill = (base0 + D) / fmaxf(1024.0f - C, 1.0f);
            if (it >= 32) break;
        }
    }

    float4* orow = reinterpret_cast<float4*>(out + (size_t)row * NCOLS);

    if (p0conv && it < 32) {
        // ---- phase 1: upper clamps (threshold scan on d = y-u) ----
        const float base1 = base0 + dsF;
        const float n1    = 1024.0f - cntF;
        const float NEG_INF = __int_as_float(0xff800000);

        float dd[EPL];
        #pragma unroll
        for (int e = 0; e < EPL; e++)
            dd[e] = (yv[e] < maskT0) ? NEG_INF : (yv[e] - uv[e]);

        float maskT1 = 0.0f;
        {
            float prev1 = -1.0f;
            for (;;) {
                ++it;
                const int pb = it & 1;
                const float T = -fill;
                float c = 0.0f, a = 0.0f;
                #pragma unroll
                for (int e = 0; e < EPL; e++) {
                    const bool p = dd[e] > T;
                    c += p ? 1.0f : 0.0f;
                    a += p ? dd[e] : 0.0f;
                }
                #pragma unroll
                for (int o = 16; o; o >>= 1) {
                    c += __shfl_xor_sync(0xffffffffu, c, o);
                    a += __shfl_xor_sync(0xffffffffu, a, o);
                }
                if (lane == 0) red[pb][wid] = make_float2(c, a);
                __syncthreads();
                const float C = red[pb][0].x + red[pb][1].x + red[pb][2].x + red[pb][3].x;
                const float A = red[pb][0].y + red[pb][1].y + red[pb][2].y + red[pb][3].y;
                maskT1 = T;
                if (C == prev1) break;
                prev1 = C;
                fill = (base1 + A) / fmaxf(n1 - C, 1.0f);
                if (it >= 32) break;
            }
        }

        // epilogue: lower -> 0, upper -> u (= y - dd), else y + fill
        float o4[EPL];
        #pragma unroll
        for (int e = 0; e < EPL; e++)
            o4[e] = (yv[e] < maskT0) ? 0.0f
                  : ((dd[e] > maskT1) ? (yv[e] - dd[e]) : (yv[e] + fill));
        float4 v0, v1;
        v0.x=o4[0]; v0.y=o4[1]; v0.z=o4[2]; v0.w=o4[3];
        v1.x=o4[4]; v1.y=o4[5]; v1.z=o4[6]; v1.w=o4[7];
        orow[t] = v0; orow[t + 128] = v1;
    } else {
        // phase 1 never ran (budget exhausted in phase 0)
        float o4[EPL];
        #pragma unroll
        for (int e = 0; e < EPL; e++)
            o4[e] = (yv[e] < maskT0) ? 0.0f : (yv[e] + fill);
        float4 v0, v1;
        v0.x=o4[0]; v0.y=o4[1]; v0.z=o4[2]; v0.w=o4[3];
        v1.x=o4[4]; v1.y=o4[5]; v1.z=o4[6]; v1.w=o4[7];
        orow[t] = v0; orow[t + 128] = v1;
    }
}

extern "C" void kernel_launch(void* const* d_in, const int* in_sizes, int n_in,
                              void* d_out, int out_size) {
    const float* y     = (const float*)d_in[0];
    const float* upper = (const float*)d_in[1];
    float*       out   = (float*)d_out;
    const int rows = in_sizes[0] / NCOLS;    // 2048
    proj_kernel<<<rows, THREADS>>>(y, upper, out);
}

// round 5
// speedup vs baseline: 1.0194x; 1.0194x over previous
#include <cuda_runtime.h>

// Batched active-set (water-filling) projection — 2 rows per warp, warp-private.
// Threshold-set formulation: phase-0 fill monotone decreasing -> lower set =
// {y < -fill}; phase-1 fill monotone increasing -> upper set = {y-u > -fill}.
// Per iteration: predicated 32-elem scan per row, fixed-point REDUX.ADD
// reductions (count int + 2^18-scaled sum), __fdividef water level.
// Lower-clamped elements are poisoned to -INF in yv (implicit mask).
// No shared memory, no __syncthreads; the two rows' chains interleave for ILP.

#define NCOLS 1024
#define EPL 32
#define ROWS_PER_WARP 2
#define WARPS_PER_BLOCK 2
#define THREADS (WARPS_PER_BLOCK * 32)

__global__ __launch_bounds__(THREADS)
void proj_kernel(const float* __restrict__ y,
                 const float* __restrict__ upper,
                 float* __restrict__ out) {
    const int lane = threadIdx.x & 31;
    const int warp = blockIdx.x * WARPS_PER_BLOCK + (threadIdx.x >> 5);
    const int row0 = warp * ROWS_PER_WARP;

    const float SCALE    = 262144.0f;           // 2^18
    const float INVSCALE = 1.0f / 262144.0f;
    const float NEG_INF  = __int_as_float(0xff800000);
    const float POS_INF  = __int_as_float(0x7f800000);

    // upper is shared across all rows: load once
    float uv[EPL];
    {
        const float4* urow = reinterpret_cast<const float4*>(upper);
        #pragma unroll
        for (int k = 0; k < 8; k++) {
            const float4 b = urow[lane + 32 * k];
            uv[4*k+0]=b.x; uv[4*k+1]=b.y; uv[4*k+2]=b.z; uv[4*k+3]=b.w;
        }
    }

    float yv[ROWS_PER_WARP][EPL];
    #pragma unroll
    for (int r = 0; r < ROWS_PER_WARP; r++) {
        const float4* yrow = reinterpret_cast<const float4*>(y + (size_t)(row0 + r) * NCOLS);
        #pragma unroll
        for (int k = 0; k < 8; k++) {
            const float4 a = yrow[lane + 32 * k];
            yv[r][4*k+0]=a.x; yv[r][4*k+1]=a.y; yv[r][4*k+2]=a.z; yv[r][4*k+3]=a.w;
        }
    }

    float fill[ROWS_PER_WARP], baseC[ROWS_PER_WARP], nC[ROWS_PER_WARP], T1[ROWS_PER_WARP];
    int   prev[ROWS_PER_WARP], phase[ROWS_PER_WARP], iter[ROWS_PER_WARP];

    #pragma unroll
    for (int r = 0; r < ROWS_PER_WARP; r++) {
        float s = 0.0f;
        #pragma unroll
        for (int e = 0; e < EPL; e++) s += yv[r][e];
        const int si = __reduce_add_sync(0xffffffffu, __float2int_rn(s * SCALE));
        const float s0 = (float)si * INVSCALE;
        baseC[r] = 512.0f - s0;
        nC[r]    = 1024.0f;
        fill[r]  = baseC[r] * (1.0f / 1024.0f);
        prev[r]  = 0; phase[r] = 0; iter[r] = 0;
        T1[r]    = POS_INF;                        // +INF => no upper clamping
    }

    for (;;) {
        bool act[ROWS_PER_WARP];
        act[0] = (phase[0] < 2) & (iter[0] < 32);
        act[1] = (phase[1] < 2) & (iter[1] < 32);
        if (!(act[0] | act[1])) break;

        float T[ROWS_PER_WARP];
        int   c[ROWS_PER_WARP];
        float D[ROWS_PER_WARP];

        // scans (warp-uniform branches; two rows independent -> ILP)
        #pragma unroll
        for (int r = 0; r < ROWS_PER_WARP; r++) {
            T[r] = -fill[r];
            int cc = 0; float dd = 0.0f;
            if (act[r]) {
                if (phase[r] == 0) {
                    #pragma unroll
                    for (int e = 0; e < EPL; e++) {
                        const bool p = yv[r][e] < T[r];
                        cc += p;
                        dd += p ? yv[r][e] : 0.0f;
                    }
                } else {
                    #pragma unroll
                    for (int e = 0; e < EPL; e++) {
                        const float d = yv[r][e] - uv[e];   // -INF for lower-clamped
                        const bool p = d > T[r];
                        cc += p;
                        dd += p ? d : 0.0f;
                    }
                }
            }
            c[r] = cc; D[r] = dd;
        }

        // reductions: both rows' REDUXes issue together and overlap
        int   cr[ROWS_PER_WARP];
        float Dr[ROWS_PER_WARP];
        {
            const int d0 = __float2int_rn(D[0] * SCALE);
            const int d1 = __float2int_rn(D[1] * SCALE);
            cr[0] = __reduce_add_sync(0xffffffffu, c[0]);
            cr[1] = __reduce_add_sync(0xffffffffu, c[1]);
            const int s0 = __reduce_add_sync(0xffffffffu, d0);
            const int s1 = __reduce_add_sync(0xffffffffu, d1);
            Dr[0] = (float)s0 * INVSCALE;
            Dr[1] = (float)s1 * INVSCALE;
        }

        // state update (warp-uniform)
        #pragma unroll
        for (int r = 0; r < ROWS_PER_WARP; r++) {
            if (!act[r]) continue;
            iter[r]++;
            if (cr[r] == prev[r]) {
                if (phase[r] == 0) {
                    // phase advance: freeze lower set (poison), re-base for phase 1
                    #pragma unroll
                    for (int e = 0; e < EPL; e++)
                        if (yv[r][e] < T[r]) yv[r][e] = NEG_INF;
                    baseC[r] += Dr[r];
                    nC[r]    -= (float)cr[r];
                    prev[r]   = 0;
                    phase[r]  = 1;
                    // fill unchanged: (baseC)/(nC) == current fill at convergence
                } else {
                    T1[r]    = T[r];
                    phase[r] = 2;
                }
            } else {
                prev[r] = cr[r];
                fill[r] = __fdividef(baseC[r] + Dr[r],
                                     fmaxf(nC[r] - (float)cr[r], 1.0f));
                if (iter[r] >= 32) {
                    // budget exhausted mid-phase: round-32 clamps were accepted
                    if (phase[r] == 0) {
                        #pragma unroll
                        for (int e = 0; e < EPL; e++)
                            if (yv[r][e] < T[r]) yv[r][e] = NEG_INF;
                        // T1 stays +INF: phase 1 never ran
                    } else {
                        T1[r] = T[r];
                    }
                }
            }
        }
    }

    // epilogue: lower (-INF) -> 0, upper (y-u > T1) -> u, else y + fill
    #pragma unroll
    for (int r = 0; r < ROWS_PER_WARP; r++) {
        float4* orow = reinterpret_cast<float4*>(out + (size_t)(row0 + r) * NCOLS);
        #pragma unroll
        for (int k = 0; k < 8; k++) {
            float o4[4];
            #pragma unroll
            for (int j = 0; j < 4; j++) {
                const int e = 4 * k + j;
                const float yy = yv[r][e];
                o4[j] = (yy == NEG_INF) ? 0.0f
                      : ((yy - uv[e] > T1[r]) ? uv[e] : yy + fill[r]);
            }
            float4 v; v.x=o4[0]; v.y=o4[1]; v.z=o4[2]; v.w=o4[3];
            orow[lane + 32 * k] = v;
        }
    }
}

extern "C" void kernel_launch(void* const* d_in, const int* in_sizes, int n_in,
                              void* d_out, int out_size) {
    const float* y     = (const float*)d_in[0];
    const float* upper = (const float*)d_in[1];
    float*       out   = (float*)d_out;
    const int rows   = in_sizes[0] / NCOLS;                       // 2048
    const int warps  = (rows + ROWS_PER_WARP - 1) / ROWS_PER_WARP; // 1024
    const int blocks = (warps + WARPS_PER_BLOCK - 1) / WARPS_PER_BLOCK;
    proj_kernel<<<blocks, THREADS>>>(y, upper, out);
}

// round 7
// speedup vs baseline: 1.3721x; 1.3459x over previous
#include <cuda_runtime.h>

// Batched active-set (water-filling) projection — warp-per-row, threshold-set
// formulation (matches the reference's two-phase trajectory exactly):
//   phase 0: fill monotone decreasing  -> lower set = {y < -fill}
//   phase 1: fill monotone increasing  -> upper set = {y-u > -fill} over the
//            frozen phase-0 complement
// Register diet: upper lives in shared memory (row-invariant); at the phase
// transition yv is overwritten in place with d = y-u (lower-clamped poisoned
// to -INF), and the epilogue recovers y = d + u from smem. ~60 regs -> ~2x
// occupancy vs the 128-reg variant. Reductions are exact fixed-point
// REDUX.ADD (2^18 scale); water level via __fdividef.

#define NCOLS 1024
#define EPL 32
#define WARPS_PER_BLOCK 2
#define THREADS (WARPS_PER_BLOCK * 32)

__global__ __launch_bounds__(THREADS)
void proj_kernel(const float* __restrict__ y,
                 const float* __restrict__ upper,
                 float* __restrict__ out) {
    const int lane = threadIdx.x & 31;
    const int row  = blockIdx.x * WARPS_PER_BLOCK + (threadIdx.x >> 5);

    __shared__ float su[NCOLS];
    {
        const float4* u4 = reinterpret_cast<const float4*>(upper);
        float4*       s4 = reinterpret_cast<float4*>(su);
        #pragma unroll
        for (int k = 0; k < 4; k++)
            s4[threadIdx.x + THREADS * k] = u4[threadIdx.x + THREADS * k];
    }
    __syncthreads();   // one-time; warps fully independent afterwards

    const float SCALE    = 262144.0f;           // 2^18
    const float INVSCALE = 1.0f / 262144.0f;
    const float NEG_INF  = __int_as_float(0xff800000);

    float yv[EPL];
    {
        const float4* yrow = reinterpret_cast<const float4*>(y + (size_t)row * NCOLS);
        #pragma unroll
        for (int k = 0; k < 8; k++) {
            const float4 a = yrow[lane + 32 * k];
            yv[4*k+0]=a.x; yv[4*k+1]=a.y; yv[4*k+2]=a.z; yv[4*k+3]=a.w;
        }
    }

    // s0 = sum(y) (exact order-independent fixed-point reduce)
    float s0;
    {
        float s = 0.0f;
        #pragma unroll
        for (int e = 0; e < EPL; e++) s += yv[e];
        const int si = __reduce_add_sync(0xffffffffu, __float2int_rn(s * SCALE));
        s0 = (float)si * INVSCALE;
    }

    const float base0 = 512.0f - s0;
    float fill = base0 * (1.0f / 1024.0f);

    int   it = 0;
    float maskT0 = 0.0f;
    bool  p0conv = false;
    float cntF = 0.0f, dsF = 0.0f;

    // ---- phase 0: lower clamps (threshold scan on y) ----
    {
        int prev = 0;
        for (;;) {
            ++it;
            const float T = -fill;
            int c = 0; float d = 0.0f;
            #pragma unroll
            for (int e = 0; e < EPL; e++) {
                const bool p = yv[e] < T;
                c += p;
                d += p ? yv[e] : 0.0f;
            }
            const int cr = __reduce_add_sync(0xffffffffu, c);
            const int dr = __reduce_add_sync(0xffffffffu, __float2int_rn(d * SCALE));
            const float D = (float)dr * INVSCALE;
            maskT0 = T; cntF = (float)cr; dsF = D;
            if (cr == prev) { p0conv = true; break; }   // phase-advance round
            prev = cr;
            fill = __fdividef(base0 + D, fmaxf(1024.0f - (float)cr, 1.0f));
            if (it >= 32) break;                         // budget exhausted
        }
    }

    float4* orow = reinterpret_cast<float4*>(out + (size_t)row * NCOLS);
    const float4* su4 = reinterpret_cast<const float4*>(su);

    if (p0conv && it < 32) {
        // phase transition: yv <- d = y-u (free) / -INF (lower-clamped)
        #pragma unroll
        for (int k = 0; k < 8; k++) {
            const float4 u4 = su4[lane + 32 * k];
            const float uu[4] = {u4.x, u4.y, u4.z, u4.w};
            #pragma unroll
            for (int j = 0; j < 4; j++) {
                const int e = 4 * k + j;
                yv[e] = (yv[e] < maskT0) ? NEG_INF : (yv[e] - uu[j]);
            }
        }
        const float base1 = base0 + dsF;
        const float n1    = 1024.0f - cntF;

        // ---- phase 1: upper clamps (threshold scan on d) ----
        float maskT1 = 0.0f;
        {
            int prev1 = 0;
            for (;;) {
                ++it;
                const float T = -fill;
                int c = 0; float a = 0.0f;
                #pragma unroll
                for (int e = 0; e < EPL; e++) {
                    const bool p = yv[e] > T;
                    c += p;
                    a += p ? yv[e] : 0.0f;
                }
                const int cr = __reduce_add_sync(0xffffffffu, c);
                const int ar = __reduce_add_sync(0xffffffffu, __float2int_rn(a * SCALE));
                const float A = (float)ar * INVSCALE;
                maskT1 = T;
                if (cr == prev1) break;
                prev1 = cr;
                fill = __fdividef(base1 + A, fmaxf(n1 - (float)cr, 1.0f));
                if (it >= 32) break;
            }
        }

        // epilogue: yv holds d. lower (-INF) -> 0; upper (d > T1) -> u;
        // free -> y + fill = d + u + fill
        #pragma unroll
        for (int k = 0; k < 8; k++) {
            const float4 u4 = su4[lane + 32 * k];
            const float uu[4] = {u4.x, u4.y, u4.z, u4.w};
            float o4[4];
            #pragma unroll
            for (int j = 0; j < 4; j++) {
                const int e = 4 * k + j;
                const float d = yv[e];
                o4[j] = (d == NEG_INF) ? 0.0f
                      : ((d > maskT1) ? uu[j] : d + uu[j] + fill);
            }
            float4 v; v.x=o4[0]; v.y=o4[1]; v.z=o4[2]; v.w=o4[3];
            orow[lane + 32 * k] = v;
        }
    } else {
        // phase 1 never ran (budget exhausted in phase 0)
        #pragma unroll
        for (int k = 0; k < 8; k++) {
            float o4[4];
            #pragma unroll
            for (int j = 0; j < 4; j++) {
                const int e = 4 * k + j;
                o4[j] = (yv[e] < maskT0) ? 0.0f : yv[e] + fill;
            }
            float4 v; v.x=o4[0]; v.y=o4[1]; v.z=o4[2]; v.w=o4[3];
            orow[lane + 32 * k] = v;
        }
    }
}

extern "C" void kernel_launch(void* const* d_in, const int* in_sizes, int n_in,
                              void* d_out, int out_size) {
    const float* y     = (const float*)d_in[0];
    const float* upper = (const float*)d_in[1];
    float*       out   = (float*)d_out;
    const int rows   = in_sizes[0] / NCOLS;                      // 2048
    const int blocks = (rows + WARPS_PER_BLOCK - 1) / WARPS_PER_BLOCK;
    proj_kernel<<<blocks, THREADS>>>(y, upper, out);
}